// round 7
// baseline (speedup 1.0000x reference)
#include <cuda_runtime.h>
#include <cstdint>
#include <cstddef>

#define TSTEPS 32
#define INF    27
#define HID    10
#define XPAD   28            // x row padded to 28 floats (16B-aligned rows)

__device__ __forceinline__ void cp4(uint32_t saddr, const void* gptr){
  asm volatile("cp.async.ca.shared.global [%0], [%1], 4;" :: "r"(saddr), "l"(gptr));
}
// packed f32x2 fma: acc.lo += a.lo*b.lo, acc.hi += a.hi*b.hi (in-place)
__device__ __forceinline__ void ffma2(unsigned long long& acc,
                                      unsigned long long a, unsigned long long b){
  asm("fma.rn.f32x2 %0, %1, %2, %0;" : "+l"(acc) : "l"(a), "l"(b));
}
__device__ __forceinline__ float2 unpk2(unsigned long long v){
  float2 r;
  asm("mov.b64 {%0, %1}, %2;" : "=f"(r.x), "=f"(r.y) : "l"(v));
  return r;
}
__device__ __forceinline__ unsigned long long pk2(float a, float b){
  unsigned long long r;
  asm("mov.b64 %0, {%1, %2};" : "=l"(r) : "f"(a), "f"(b));
  return r;
}
// sigmoid / tanh via MUFU.EX2 + MUFU.RCP (near-full precision; rel_err 5e-8 proven)
__device__ __forceinline__ float sigf(float v){
  return __fdividef(1.f, 1.f + __expf(-v));
}
__device__ __forceinline__ float tanhfast(float v){
  return __fdividef(2.f, 1.f + __expf(-2.f*v)) - 1.f;
}

// 128 threads/block. Lane pairs (2p, 2p+1) share batch elements {2p, 2p+1};
// lane parity selects which 5 hidden units it computes (split-k, R6 topology).
// NEW: dot products run on fma.rn.f32x2 packed over the j (reduction) axis —
// weights and x load as naturally-contiguous pairs, no operand duplication.
__global__ void __launch_bounds__(128) lstm_fused_kernel(
    const float* __restrict__ word,
    const float* __restrict__ W_ih, const float* __restrict__ W_hh,
    const float* __restrict__ b_ih, const float* __restrict__ b_hh,
    const float* __restrict__ W_fc, const float* __restrict__ b_fc,
    const float* __restrict__ W_out, const float* __restrict__ b_out,
    float* __restrict__ out, int Bn)
{
  // scalar weights, rows padded (pad = 0) and 16B-aligned
  __shared__ __align__(16) float s_wih[40*28];  // row r: r*28 + j, j<27
  __shared__ __align__(16) float s_whh[40*12];  // row r: r*12 + j, j<10
  __shared__ float s_bias[40];                  // b_ih + b_hh
  __shared__ float s_wfc[50], s_bfc[5], s_wout[5], s_bout[1];
  __shared__ __align__(16) float s_x[2][128*XPAD];  // double-buffered, padded rows

  const int tid  = threadIdx.x;
  const int half = tid & 1;        // which 5 k's this lane owns (0..4 or 5..9)
  const int p    = tid >> 1;       // pair index (0..63)
  const int kb   = half * 5;

  for (int idx = tid; idx < 40*28; idx += 128){
    int r = idx / 28, j = idx - r*28;
    s_wih[idx] = (j < 27) ? W_ih[r*27 + j] : 0.f;
  }
  for (int idx = tid; idx < 40*12; idx += 128){
    int r = idx / 12, j = idx - r*12;
    s_whh[idx] = (j < 10) ? W_hh[r*10 + j] : 0.f;
  }
  if (tid < 40) s_bias[tid] = b_ih[tid] + b_hh[tid];
  if (tid < 50) s_wfc[tid] = W_fc[tid];
  if (tid < 5) { s_bfc[tid] = b_fc[tid]; s_wout[tid] = W_out[tid]; }
  if (tid == 0) s_bout[0] = b_out[0];
  // zero the pad column j=27 of both x buffers (never written by staging)
  s_x[0][tid*XPAD + 27] = 0.f;
  s_x[1][tid*XPAD + 27] = 0.f;
  __syncthreads();   // pad zeros + weights visible before first use

  const int blockElem = blockIdx.x * 128;
  const uint32_t sx0 = (uint32_t)__cvta_generic_to_shared(&s_x[0][0]);
  const uint32_t myRowOff = (uint32_t)(tid * XPAD * 4);

  // stage t=0 into buffer 0: thread r copies row r (27 x 4B cp.async)
  {
    const float* src = word + ((size_t)blockElem + tid) * INF;
    #pragma unroll
    for (int j = 0; j < 27; j++)
      cp4(sx0 + myRowOff + (uint32_t)(j*4), src + j);
    asm volatile("cp.async.commit_group;");
  }

  // recurrent state: full h scalars (rebuilt via shfl), packed h pairs for fma,
  // own-c only (5 k x 2 elems)
  float hA[10], hB[10], cA[5], cB[5];
  unsigned long long hA2[6], hB2[6];      // 5 real pairs + 1 zero pad (hh rows padded to 12)
  #pragma unroll
  for (int k = 0; k < 10; k++){ hA[k]=0.f; hB[k]=0.f; }
  #pragma unroll
  for (int k = 0; k < 6;  k++){ hA2[k]=0ull; hB2[k]=0ull; }
  #pragma unroll
  for (int k = 0; k < 5;  k++){ cA[k]=0.f; cB[k]=0.f; }

  const float* wih_b  = s_wih + kb*28;
  const float* whh_b  = s_whh + kb*12;
  const float* bias_b = s_bias + kb;

  #pragma unroll 1
  for (int t = 0; t < TSTEPS; t++){
    if (t + 1 < TSTEPS){
      const float* src = word + ((size_t)(t+1)*Bn + blockElem + tid) * INF;
      uint32_t dst = sx0 + (uint32_t)(((t+1)&1) * (128*XPAD*4)) + myRowOff;
      #pragma unroll
      for (int j = 0; j < 27; j++)
        cp4(dst + (uint32_t)(j*4), src + j);
      asm volatile("cp.async.commit_group;");
      asm volatile("cp.async.wait_group 1;");
    } else {
      asm volatile("cp.async.wait_group 0;");
    }
    __syncthreads();

    // packed x rows for pair elements 2p, 2p+1 (14 u64 each; slot 13.hi = 0 pad)
    const unsigned long long* xpA =
        (const unsigned long long*)&s_x[t & 1][(2*p    ) * XPAD];
    const unsigned long long* xpB =
        (const unsigned long long*)&s_x[t & 1][(2*p + 1) * XPAD];
    unsigned long long xA2[14], xB2[14];
    #pragma unroll
    for (int m = 0; m < 7; m++){
      ulonglong2 a = ((const ulonglong2*)xpA)[m];
      ulonglong2 b = ((const ulonglong2*)xpB)[m];
      xA2[2*m] = a.x; xA2[2*m+1] = a.y;
      xB2[2*m] = b.x; xB2[2*m+1] = b.y;
    }

    float hnA[5], hnB[5];
    #pragma unroll
    for (int kk = 0; kk < 5; kk++){
      unsigned long long aiA=0ull, aiB=0ull, afA=0ull, afB=0ull;
      unsigned long long agA=0ull, agB=0ull, aoA=0ull, aoB=0ull;
      const ulonglong2* wi = (const ulonglong2*)(wih_b + (kk     )*28);
      const ulonglong2* wf = (const ulonglong2*)(wih_b + (kk + 10)*28);
      const ulonglong2* wg = (const ulonglong2*)(wih_b + (kk + 20)*28);
      const ulonglong2* wo = (const ulonglong2*)(wih_b + (kk + 30)*28);
      #pragma unroll
      for (int m = 0; m < 7; m++){
        ulonglong2 vi = wi[m], vf = wf[m], vg = wg[m], vo = wo[m];
        unsigned long long xa0 = xA2[2*m], xa1 = xA2[2*m+1];
        unsigned long long xb0 = xB2[2*m], xb1 = xB2[2*m+1];
        ffma2(aiA, vi.x, xa0); ffma2(aiA, vi.y, xa1);
        ffma2(aiB, vi.x, xb0); ffma2(aiB, vi.y, xb1);
        ffma2(afA, vf.x, xa0); ffma2(afA, vf.y, xa1);
        ffma2(afB, vf.x, xb0); ffma2(afB, vf.y, xb1);
        ffma2(agA, vg.x, xa0); ffma2(agA, vg.y, xa1);
        ffma2(agB, vg.x, xb0); ffma2(agB, vg.y, xb1);
        ffma2(aoA, vo.x, xa0); ffma2(aoA, vo.y, xa1);
        ffma2(aoB, vo.x, xb0); ffma2(aoB, vo.y, xb1);
      }
      const ulonglong2* ui = (const ulonglong2*)(whh_b + (kk     )*12);
      const ulonglong2* uf = (const ulonglong2*)(whh_b + (kk + 10)*12);
      const ulonglong2* ug = (const ulonglong2*)(whh_b + (kk + 20)*12);
      const ulonglong2* uo = (const ulonglong2*)(whh_b + (kk + 30)*12);
      #pragma unroll
      for (int m = 0; m < 3; m++){
        ulonglong2 vi = ui[m], vf = uf[m], vg = ug[m], vo = uo[m];
        unsigned long long ha0 = hA2[2*m], ha1 = hA2[2*m+1];
        unsigned long long hb0 = hB2[2*m], hb1 = hB2[2*m+1];
        ffma2(aiA, vi.x, ha0); ffma2(aiA, vi.y, ha1);
        ffma2(aiB, vi.x, hb0); ffma2(aiB, vi.y, hb1);
        ffma2(afA, vf.x, ha0); ffma2(afA, vf.y, ha1);
        ffma2(afB, vf.x, hb0); ffma2(afB, vf.y, hb1);
        ffma2(agA, vg.x, ha0); ffma2(agA, vg.y, ha1);
        ffma2(agB, vg.x, hb0); ffma2(agB, vg.y, hb1);
        ffma2(aoA, vo.x, ha0); ffma2(aoA, vo.y, ha1);
        ffma2(aoB, vo.x, hb0); ffma2(aoB, vo.y, hb1);
      }
      // horizontal reduce + bias
      float2 vi0 = unpk2(aiA), vi1 = unpk2(aiB);
      float2 vf0 = unpk2(afA), vf1 = unpk2(afB);
      float2 vg0 = unpk2(agA), vg1 = unpk2(agB);
      float2 vo0 = unpk2(aoA), vo1 = unpk2(aoB);
      float bi = bias_b[kk], bf = bias_b[kk+10], bg = bias_b[kk+20], bo = bias_b[kk+30];
      float ai0 = (vi0.x + vi0.y) + bi, ai1 = (vi1.x + vi1.y) + bi;
      float af0 = (vf0.x + vf0.y) + bf, af1 = (vf1.x + vf1.y) + bf;
      float ag0 = (vg0.x + vg0.y) + bg, ag1 = (vg1.x + vg1.y) + bg;
      float ao0 = (vo0.x + vo0.y) + bo, ao1 = (vo1.x + vo1.y) + bo;

      float i0 = sigf(ai0), i1 = sigf(ai1);
      float f0 = sigf(af0), f1 = sigf(af1);
      float g0 = tanhfast(ag0), g1 = tanhfast(ag1);
      float o0 = sigf(ao0), o1 = sigf(ao1);
      float cn0 = fmaf(f0, cA[kk], i0*g0);
      float cn1 = fmaf(f1, cB[kk], i1*g1);
      float hv0 = o0 * tanhfast(cn0);
      float hv1 = o1 * tanhfast(cn1);
      cA[kk]  = fmaxf(cn0, 0.f);       // ReLU on carried cell state
      cB[kk]  = fmaxf(cn1, 0.f);
      hnA[kk] = fmaxf(hv0, 0.f);       // ReLU on carried hidden
      hnB[kk] = fmaxf(hv1, 0.f);
    }
    // exchange halves with pair partner -> full h (scalars), then repack pairs
    const int ob = 5 - kb;             // partner's k-base (0 <-> 5)
    #pragma unroll
    for (int kk = 0; kk < 5; kk++){
      float oA = __shfl_xor_sync(0xFFFFFFFFu, hnA[kk], 1);
      float oB = __shfl_xor_sync(0xFFFFFFFFu, hnB[kk], 1);
      hA[kb + kk] = hnA[kk];  hA[ob + kk] = oA;
      hB[kb + kk] = hnB[kk];  hB[ob + kk] = oB;
    }
    #pragma unroll
    for (int m = 0; m < 5; m++){
      hA2[m] = pk2(hA[2*m], hA[2*m+1]);
      hB2[m] = pk2(hB[2*m], hB[2*m+1]);
    }
    __syncthreads();   // all reads of this x buffer done before re-staging
  }

  // ---- head: FC(10->5) -> ReLU -> Linear(5->1) -> sigmoid ----
  if (half == 0){
    float z0 = s_bout[0], z1 = s_bout[0];
    #pragma unroll
    for (int u = 0; u < 5; u++){
      float y0 = s_bfc[u], y1 = s_bfc[u];
      #pragma unroll
      for (int k = 0; k < 10; k++){
        float w = s_wfc[u*10 + k];
        y0 = fmaf(w, hA[k], y0);
        y1 = fmaf(w, hB[k], y1);
      }
      z0 = fmaf(s_wout[u], fmaxf(y0, 0.f), z0);
      z1 = fmaf(s_wout[u], fmaxf(y1, 0.f), z1);
    }
    const int b0 = blockElem + 2*p;
    if (b0 + 1 < Bn){
      float2 v; v.x = sigf(z0); v.y = sigf(z1);
      *(float2*)(out + b0) = v;                 // coalesced 8B store
    } else if (b0 < Bn){
      out[b0] = sigf(z0);
    }
  }
}

extern "C" void kernel_launch(void* const* d_in, const int* in_sizes, int n_in,
                              void* d_out, int out_size) {
  const float* word  = (const float*)d_in[0];
  const float* W_ih  = (const float*)d_in[1];
  const float* W_hh  = (const float*)d_in[2];
  const float* b_ih  = (const float*)d_in[3];
  const float* b_hh  = (const float*)d_in[4];
  const float* W_fc  = (const float*)d_in[5];
  const float* b_fc  = (const float*)d_in[6];
  const float* W_out = (const float*)d_in[7];
  const float* b_out = (const float*)d_in[8];
  float* out = (float*)d_out;

  const int Bn = in_sizes[0] / (TSTEPS * INF);   // 65536
  const int blocks = (Bn + 127) / 128;           // 512 blocks of 128 threads

  lstm_fused_kernel<<<blocks, 128>>>(word, W_ih, W_hh, b_ih, b_hh,
                                     W_fc, b_fc, W_out, b_out, out, Bn);
}

// round 8
// speedup vs baseline: 1.3280x; 1.3280x over previous
#include <cuda_runtime.h>
#include <cstdint>
#include <cstddef>

#define TSTEPS 32
#define INF    27
#define HID    10

__device__ __forceinline__ void cp8(uint32_t saddr, const void* gptr){
  asm volatile("cp.async.ca.shared.global [%0], [%1], 8;" :: "r"(saddr), "l"(gptr));
}
// single-instruction tanh (MUFU.TANH, sm_75+)
__device__ __forceinline__ float tanh_fast(float x){
  float r;
  asm("tanh.approx.f32 %0, %1;" : "=f"(r) : "f"(x));
  return r;
}
// sigmoid from a PRE-HALVED preactivation: acc already holds x/2
//   sigma(x) = 0.5 + 0.5*tanh(x/2)  -> 1 MUFU + 1 FMA
__device__ __forceinline__ float sig_from_half(float acc_half){
  return fmaf(0.5f, tanh_fast(acc_half), 0.5f);
}

// 128 threads/block. Lane pairs (2p, 2p+1) share batch elements {2p, 2p+1};
// lane parity selects which 5 hidden units it computes (split-k, R6 topology).
// Activations: MUFU.TANH; i/f/o gate weights+bias pre-scaled by 0.5 in smem.
__global__ void __launch_bounds__(128) lstm_fused_kernel(
    const float* __restrict__ word,
    const float* __restrict__ W_ih, const float* __restrict__ W_hh,
    const float* __restrict__ b_ih, const float* __restrict__ b_hh,
    const float* __restrict__ W_fc, const float* __restrict__ b_fc,
    const float* __restrict__ W_out, const float* __restrict__ b_out,
    float* __restrict__ out, int Bn)
{
  // scalar weights, rows padded for LDS.128-friendly immediate offsets.
  // Gate row order r in [0,40): [0,10)=i, [10,20)=f, [20,30)=g, [30,40)=o.
  // i/f/o rows stored pre-multiplied by 0.5 (sigmoid-via-tanh identity).
  __shared__ __align__(16) float s_wih[40*28];  // row r: r*28 + j, j<27, pad 0
  __shared__ __align__(16) float s_whh[40*12];  // row r: r*12 + j, j<10, pad 0
  __shared__ float s_bias[40];                  // (b_ih + b_hh), i/f/o halved
  __shared__ float s_wfc[50], s_bfc[5], s_wout[5], s_bout[1];
  __shared__ __align__(16) float s_x[2][128*INF];  // double-buffered x staging

  const int tid  = threadIdx.x;
  const int half = tid & 1;        // which 5 k's this lane owns (0..4 or 5..9)
  const int p    = tid >> 1;       // pair index (0..63)
  const int kb   = half * 5;

  for (int idx = tid; idx < 40*28; idx += 128){
    int r = idx / 28, j = idx - r*28;
    float sc = (r < 20 || r >= 30) ? 0.5f : 1.0f;   // halve i,f,o rows
    s_wih[idx] = (j < 27) ? sc * W_ih[r*27 + j] : 0.f;
  }
  for (int idx = tid; idx < 40*12; idx += 128){
    int r = idx / 12, j = idx - r*12;
    float sc = (r < 20 || r >= 30) ? 0.5f : 1.0f;
    s_whh[idx] = (j < 10) ? sc * W_hh[r*10 + j] : 0.f;
  }
  if (tid < 40){
    float sc = (tid < 20 || tid >= 30) ? 0.5f : 1.0f;
    s_bias[tid] = sc * (b_ih[tid] + b_hh[tid]);
  }
  if (tid < 50) s_wfc[tid] = W_fc[tid];
  if (tid < 5) { s_bfc[tid] = b_fc[tid]; s_wout[tid] = W_out[tid]; }
  if (tid == 0) s_bout[0] = b_out[0];

  const int blockElem = blockIdx.x * 128;
  const uint32_t sx0 = (uint32_t)__cvta_generic_to_shared(&s_x[0][0]);

  // stage t=0 into buffer 0 (1728 float2 per block-step, 128 threads)
  {
    const float2* src = (const float2*)(word + ((size_t)blockElem) * INF);
    #pragma unroll
    for (int m = 0; m < 14; m++){
      int i2 = m*128 + tid;
      if (i2 < 1728) cp8(sx0 + (uint32_t)(i2*8), src + i2);
    }
    asm volatile("cp.async.commit_group;");
  }

  // full h for both elements (rebuilt each step via shfl exchange),
  // own-c only (5 k x 2 elems)
  float hA[10], hB[10], cA[5], cB[5];
  #pragma unroll
  for (int k = 0; k < 10; k++){ hA[k]=0.f; hB[k]=0.f; }
  #pragma unroll
  for (int k = 0; k < 5;  k++){ cA[k]=0.f; cB[k]=0.f; }

  // lane-local weight bases (kb is uniform per lane; hoisted out of the loop)
  const float* wih_b  = s_wih + kb*28;
  const float* whh_b  = s_whh + kb*12;
  const float* bias_b = s_bias + kb;

  #pragma unroll 1
  for (int t = 0; t < TSTEPS; t++){
    if (t + 1 < TSTEPS){
      const float2* src = (const float2*)(word + ((size_t)(t+1)*Bn + blockElem) * INF);
      uint32_t dst = sx0 + (uint32_t)(((t+1)&1) * (128*INF*4));
      #pragma unroll
      for (int m = 0; m < 14; m++){
        int i2 = m*128 + tid;
        if (i2 < 1728) cp8(dst + (uint32_t)(i2*8), src + i2);
      }
      asm volatile("cp.async.commit_group;");
      asm volatile("cp.async.wait_group 1;");
    } else {
      asm volatile("cp.async.wait_group 0;");
    }
    __syncthreads();

    // x rows for pair elements 2p and 2p+1 (both lanes of a pair read the
    // same addresses -> 2-way broadcast; row stride 27 coprime w/ 32 banks)
    const float* xbA = &s_x[t & 1][(2*p    ) * INF];
    const float* xbB = &s_x[t & 1][(2*p + 1) * INF];
    float xA[27], xB[27];
    #pragma unroll
    for (int j = 0; j < 27; j++){ xA[j] = xbA[j]; xB[j] = xbB[j]; }

    float hnA[5], hnB[5];
    #pragma unroll
    for (int kk = 0; kk < 5; kk++){
      float ai0 = bias_b[kk],      ai1 = ai0;
      float af0 = bias_b[kk + 10], af1 = af0;
      float ag0 = bias_b[kk + 20], ag1 = ag0;
      float ao0 = bias_b[kk + 30], ao1 = ao0;
      #pragma unroll
      for (int j = 0; j < 27; j++){
        float wi = wih_b[(kk     )*28 + j];
        float wf = wih_b[(kk + 10)*28 + j];
        float wg = wih_b[(kk + 20)*28 + j];
        float wo = wih_b[(kk + 30)*28 + j];
        float xa = xA[j], xb = xB[j];
        ai0 = fmaf(wi, xa, ai0);  ai1 = fmaf(wi, xb, ai1);
        af0 = fmaf(wf, xa, af0);  af1 = fmaf(wf, xb, af1);
        ag0 = fmaf(wg, xa, ag0);  ag1 = fmaf(wg, xb, ag1);
        ao0 = fmaf(wo, xa, ao0);  ao1 = fmaf(wo, xb, ao1);
      }
      #pragma unroll
      for (int j = 0; j < 10; j++){
        float ui = whh_b[(kk     )*12 + j];
        float uf = whh_b[(kk + 10)*12 + j];
        float ug = whh_b[(kk + 20)*12 + j];
        float uo = whh_b[(kk + 30)*12 + j];
        float ha = hA[j], hb = hB[j];
        ai0 = fmaf(ui, ha, ai0);  ai1 = fmaf(ui, hb, ai1);
        af0 = fmaf(uf, ha, af0);  af1 = fmaf(uf, hb, af1);
        ag0 = fmaf(ug, ha, ag0);  ag1 = fmaf(ug, hb, ag1);
        ao0 = fmaf(uo, ha, ao0);  ao1 = fmaf(uo, hb, ao1);
      }
      // activations: i/f/o accs hold x/2 (pre-halved weights) -> 1 MUFU + 1 FMA
      float i0 = sig_from_half(ai0), i1 = sig_from_half(ai1);
      float f0 = sig_from_half(af0), f1 = sig_from_half(af1);
      float g0 = tanh_fast(ag0),     g1 = tanh_fast(ag1);
      float o0 = sig_from_half(ao0), o1 = sig_from_half(ao1);
      float cn0 = fmaf(f0, cA[kk], i0*g0);
      float cn1 = fmaf(f1, cB[kk], i1*g1);
      float hv0 = o0 * tanh_fast(cn0);
      float hv1 = o1 * tanh_fast(cn1);
      cA[kk]  = fmaxf(cn0, 0.f);       // ReLU on carried cell state
      cB[kk]  = fmaxf(cn1, 0.f);
      hnA[kk] = fmaxf(hv0, 0.f);       // ReLU on carried hidden
      hnB[kk] = fmaxf(hv1, 0.f);
    }
    // exchange halves with pair partner -> full h for both elements
    const int ob = 5 - kb;             // partner's k-base (0 <-> 5)
    #pragma unroll
    for (int kk = 0; kk < 5; kk++){
      float oA = __shfl_xor_sync(0xFFFFFFFFu, hnA[kk], 1);
      float oB = __shfl_xor_sync(0xFFFFFFFFu, hnB[kk], 1);
      hA[kb + kk] = hnA[kk];  hA[ob + kk] = oA;
      hB[kb + kk] = hnB[kk];  hB[ob + kk] = oB;
    }
    __syncthreads();   // all reads of this x buffer done before re-staging
  }

  // ---- head: FC(10->5) -> ReLU -> Linear(5->1) -> sigmoid ----
  if (half == 0){
    float z0 = s_bout[0], z1 = s_bout[0];
    #pragma unroll
    for (int u = 0; u < 5; u++){
      float y0 = s_bfc[u], y1 = s_bfc[u];
      #pragma unroll
      for (int k = 0; k < 10; k++){
        float w = s_wfc[u*10 + k];
        y0 = fmaf(w, hA[k], y0);
        y1 = fmaf(w, hB[k], y1);
      }
      z0 = fmaf(s_wout[u], fmaxf(y0, 0.f), z0);
      z1 = fmaf(s_wout[u], fmaxf(y1, 0.f), z1);
    }
    const int b0 = blockElem + 2*p;
    // final sigmoid (z not pre-halved): 0.5 + 0.5*tanh(z/2)
    if (b0 + 1 < Bn){
      float2 v;
      v.x = fmaf(0.5f, tanh_fast(0.5f * z0), 0.5f);
      v.y = fmaf(0.5f, tanh_fast(0.5f * z1), 0.5f);
      *(float2*)(out + b0) = v;                 // coalesced 8B store
    } else if (b0 < Bn){
      out[b0] = fmaf(0.5f, tanh_fast(0.5f * z0), 0.5f);
    }
  }
}

extern "C" void kernel_launch(void* const* d_in, const int* in_sizes, int n_in,
                              void* d_out, int out_size) {
  const float* word  = (const float*)d_in[0];
  const float* W_ih  = (const float*)d_in[1];
  const float* W_hh  = (const float*)d_in[2];
  const float* b_ih  = (const float*)d_in[3];
  const float* b_hh  = (const float*)d_in[4];
  const float* W_fc  = (const float*)d_in[5];
  const float* b_fc  = (const float*)d_in[6];
  const float* W_out = (const float*)d_in[7];
  const float* b_out = (const float*)d_in[8];
  float* out = (float*)d_out;

  const int Bn = in_sizes[0] / (TSTEPS * INF);   // 65536
  const int blocks = (Bn + 127) / 128;           // 512 blocks of 128 threads

  lstm_fused_kernel<<<blocks, 128>>>(word, W_ih, W_hh, b_ih, b_hh,
                                     W_fc, b_fc, W_out, b_out, out, Bn);
}

// round 9
// speedup vs baseline: 1.3445x; 1.0125x over previous
#include <cuda_runtime.h>
#include <cstdint>
#include <cstddef>

#define TSTEPS 32
#define INF    27
#define HID    10

__device__ __forceinline__ void cp4(uint32_t saddr, const void* gptr){
  asm volatile("cp.async.ca.shared.global [%0], [%1], 4;" :: "r"(saddr), "l"(gptr));
}
// single-instruction tanh (MUFU.TANH, sm_75+)
__device__ __forceinline__ float tanh_fast(float x){
  float r;
  asm("tanh.approx.f32 %0, %1;" : "=f"(r) : "f"(x));
  return r;
}
// sigmoid from a PRE-HALVED preactivation: acc already holds x/2
//   sigma(x) = 0.5 + 0.5*tanh(x/2)  -> 1 MUFU + 1 FMA
__device__ __forceinline__ float sig_from_half(float acc_half){
  return fmaf(0.5f, tanh_fast(acc_half), 0.5f);
}

// 128 threads/block. Lane pairs (2p, 2p+1) share batch elements {2p, 2p+1};
// lane parity selects which 5 hidden units it computes (split-k).
// BARRIER-FREE main loop: thread tid stages ONLY element tid's x row, and the
// only cross-thread consumer is its pair partner (same warp) -> __syncwarp
// after cp.async.wait_group is sufficient; warps free-run and de-phase their
// MUFU bursts. No __syncthreads inside the time loop.
__global__ void __launch_bounds__(128) lstm_fused_kernel(
    const float* __restrict__ word,
    const float* __restrict__ W_ih, const float* __restrict__ W_hh,
    const float* __restrict__ b_ih, const float* __restrict__ b_hh,
    const float* __restrict__ W_fc, const float* __restrict__ b_fc,
    const float* __restrict__ W_out, const float* __restrict__ b_out,
    float* __restrict__ out, int Bn)
{
  // scalar weights, rows padded for LDS.128-friendly immediate offsets.
  // Gate row order r in [0,40): [0,10)=i, [10,20)=f, [20,30)=g, [30,40)=o.
  // i/f/o rows stored pre-multiplied by 0.5 (sigmoid-via-tanh identity).
  __shared__ __align__(16) float s_wih[40*28];  // row r: r*28 + j, j<27, pad 0
  __shared__ __align__(16) float s_whh[40*12];  // row r: r*12 + j, j<10, pad 0
  __shared__ float s_bias[40];                  // (b_ih + b_hh), i/f/o halved
  __shared__ float s_wfc[50], s_bfc[5], s_wout[5], s_bout[1];
  __shared__ __align__(16) float s_x[2][128*INF];  // double-buffered x staging

  const int tid  = threadIdx.x;
  const int half = tid & 1;        // which 5 k's this lane owns (0..4 or 5..9)
  const int p    = tid >> 1;       // pair index (0..63)
  const int kb   = half * 5;

  for (int idx = tid; idx < 40*28; idx += 128){
    int r = idx / 28, j = idx - r*28;
    float sc = (r < 20 || r >= 30) ? 0.5f : 1.0f;   // halve i,f,o rows
    s_wih[idx] = (j < 27) ? sc * W_ih[r*27 + j] : 0.f;
  }
  for (int idx = tid; idx < 40*12; idx += 128){
    int r = idx / 12, j = idx - r*12;
    float sc = (r < 20 || r >= 30) ? 0.5f : 1.0f;
    s_whh[idx] = (j < 10) ? sc * W_hh[r*10 + j] : 0.f;
  }
  if (tid < 40){
    float sc = (tid < 20 || tid >= 30) ? 0.5f : 1.0f;
    s_bias[tid] = sc * (b_ih[tid] + b_hh[tid]);
  }
  if (tid < 50) s_wfc[tid] = W_fc[tid];
  if (tid < 5) { s_bfc[tid] = b_fc[tid]; s_wout[tid] = W_out[tid]; }
  if (tid == 0) s_bout[0] = b_out[0];
  __syncthreads();   // ONE barrier: weights visible; loop itself is barrier-free

  const int blockElem = blockIdx.x * 128;
  const uint32_t sx0 = (uint32_t)__cvta_generic_to_shared(&s_x[0][0]);
  const uint32_t myRowOff = (uint32_t)(tid * INF * 4);   // this thread's own row

  // stage t=0: thread tid copies element tid's row (27 x 4B cp.async)
  {
    const float* src = word + ((size_t)blockElem + tid) * INF;
    #pragma unroll
    for (int j = 0; j < 27; j++)
      cp4(sx0 + myRowOff + (uint32_t)(j*4), src + j);
    asm volatile("cp.async.commit_group;");
  }

  // full h for both elements (rebuilt each step via shfl exchange),
  // own-c only (5 k x 2 elems)
  float hA[10], hB[10], cA[5], cB[5];
  #pragma unroll
  for (int k = 0; k < 10; k++){ hA[k]=0.f; hB[k]=0.f; }
  #pragma unroll
  for (int k = 0; k < 5;  k++){ cA[k]=0.f; cB[k]=0.f; }

  // lane-local weight bases (kb is uniform per lane; hoisted out of the loop)
  const float* wih_b  = s_wih + kb*28;
  const float* whh_b  = s_whh + kb*12;
  const float* bias_b = s_bias + kb;

  #pragma unroll 1
  for (int t = 0; t < TSTEPS; t++){
    if (t + 1 < TSTEPS){
      const float* src = word + ((size_t)(t+1)*Bn + blockElem + tid) * INF;
      uint32_t dst = sx0 + (uint32_t)(((t+1)&1) * (128*INF*4)) + myRowOff;
      #pragma unroll
      for (int j = 0; j < 27; j++)
        cp4(dst + (uint32_t)(j*4), src + j);
      asm volatile("cp.async.commit_group;");
      asm volatile("cp.async.wait_group 1;");   // own copies for step t done
    } else {
      asm volatile("cp.async.wait_group 0;");
    }
    // partner lane's copies: it executed the same wait above (lockstep);
    // __syncwarp orders our reads after its wait.
    __syncwarp();

    // x rows for pair elements 2p and 2p+1 (both lanes of a pair read the
    // same addresses -> 2-way broadcast; row stride 27 coprime w/ 32 banks)
    const float* xbA = &s_x[t & 1][(2*p    ) * INF];
    const float* xbB = &s_x[t & 1][(2*p + 1) * INF];
    float xA[27], xB[27];
    #pragma unroll
    for (int j = 0; j < 27; j++){ xA[j] = xbA[j]; xB[j] = xbB[j]; }

    float hnA[5], hnB[5];
    #pragma unroll
    for (int kk = 0; kk < 5; kk++){
      float ai0 = bias_b[kk],      ai1 = ai0;
      float af0 = bias_b[kk + 10], af1 = af0;
      float ag0 = bias_b[kk + 20], ag1 = ag0;
      float ao0 = bias_b[kk + 30], ao1 = ao0;
      #pragma unroll
      for (int j = 0; j < 27; j++){
        float wi = wih_b[(kk     )*28 + j];
        float wf = wih_b[(kk + 10)*28 + j];
        float wg = wih_b[(kk + 20)*28 + j];
        float wo = wih_b[(kk + 30)*28 + j];
        float xa = xA[j], xb = xB[j];
        ai0 = fmaf(wi, xa, ai0);  ai1 = fmaf(wi, xb, ai1);
        af0 = fmaf(wf, xa, af0);  af1 = fmaf(wf, xb, af1);
        ag0 = fmaf(wg, xa, ag0);  ag1 = fmaf(wg, xb, ag1);
        ao0 = fmaf(wo, xa, ao0);  ao1 = fmaf(wo, xb, ao1);
      }
      #pragma unroll
      for (int j = 0; j < 10; j++){
        float ui = whh_b[(kk     )*12 + j];
        float uf = whh_b[(kk + 10)*12 + j];
        float ug = whh_b[(kk + 20)*12 + j];
        float uo = whh_b[(kk + 30)*12 + j];
        float ha = hA[j], hb = hB[j];
        ai0 = fmaf(ui, ha, ai0);  ai1 = fmaf(ui, hb, ai1);
        af0 = fmaf(uf, ha, af0);  af1 = fmaf(uf, hb, af1);
        ag0 = fmaf(ug, ha, ag0);  ag1 = fmaf(ug, hb, ag1);
        ao0 = fmaf(uo, ha, ao0);  ao1 = fmaf(uo, hb, ao1);
      }
      // activations: i/f/o accs hold x/2 (pre-halved weights) -> 1 MUFU + 1 FMA
      float i0 = sig_from_half(ai0), i1 = sig_from_half(ai1);
      float f0 = sig_from_half(af0), f1 = sig_from_half(af1);
      float g0 = tanh_fast(ag0),     g1 = tanh_fast(ag1);
      float o0 = sig_from_half(ao0), o1 = sig_from_half(ao1);
      float cn0 = fmaf(f0, cA[kk], i0*g0);
      float cn1 = fmaf(f1, cB[kk], i1*g1);
      float hv0 = o0 * tanh_fast(cn0);
      float hv1 = o1 * tanh_fast(cn1);
      cA[kk]  = fmaxf(cn0, 0.f);       // ReLU on carried cell state
      cB[kk]  = fmaxf(cn1, 0.f);
      hnA[kk] = fmaxf(hv0, 0.f);       // ReLU on carried hidden
      hnB[kk] = fmaxf(hv1, 0.f);
    }
    // exchange halves with pair partner -> full h for both elements
    const int ob = 5 - kb;             // partner's k-base (0 <-> 5)
    #pragma unroll
    for (int kk = 0; kk < 5; kk++){
      float oA = __shfl_xor_sync(0xFFFFFFFFu, hnA[kk], 1);
      float oB = __shfl_xor_sync(0xFFFFFFFFu, hnB[kk], 1);
      hA[kb + kk] = hnA[kk];  hA[ob + kk] = oA;
      hB[kb + kk] = hnB[kk];  hB[ob + kk] = oB;
    }
    // no __syncthreads: buffer being overwritten next iteration was last read
    // by this warp's own lanes two iterations ago (warp-local ordering).
  }

  // ---- head: FC(10->5) -> ReLU -> Linear(5->1) -> sigmoid ----
  if (half == 0){
    float z0 = s_bout[0], z1 = s_bout[0];
    #pragma unroll
    for (int u = 0; u < 5; u++){
      float y0 = s_bfc[u], y1 = s_bfc[u];
      #pragma unroll
      for (int k = 0; k < 10; k++){
        float w = s_wfc[u*10 + k];
        y0 = fmaf(w, hA[k], y0);
        y1 = fmaf(w, hB[k], y1);
      }
      z0 = fmaf(s_wout[u], fmaxf(y0, 0.f), z0);
      z1 = fmaf(s_wout[u], fmaxf(y1, 0.f), z1);
    }
    const int b0 = blockElem + 2*p;
    // final sigmoid (z not pre-halved): 0.5 + 0.5*tanh(z/2)
    if (b0 + 1 < Bn){
      float2 v;
      v.x = fmaf(0.5f, tanh_fast(0.5f * z0), 0.5f);
      v.y = fmaf(0.5f, tanh_fast(0.5f * z1), 0.5f);
      *(float2*)(out + b0) = v;                 // coalesced 8B store
    } else if (b0 < Bn){
      out[b0] = fmaf(0.5f, tanh_fast(0.5f * z0), 0.5f);
    }
  }
}

extern "C" void kernel_launch(void* const* d_in, const int* in_sizes, int n_in,
                              void* d_out, int out_size) {
  const float* word  = (const float*)d_in[0];
  const float* W_ih  = (const float*)d_in[1];
  const float* W_hh  = (const float*)d_in[2];
  const float* b_ih  = (const float*)d_in[3];
  const float* b_hh  = (const float*)d_in[4];
  const float* W_fc  = (const float*)d_in[5];
  const float* b_fc  = (const float*)d_in[6];
  const float* W_out = (const float*)d_in[7];
  const float* b_out = (const float*)d_in[8];
  float* out = (float*)d_out;

  const int Bn = in_sizes[0] / (TSTEPS * INF);   // 65536
  const int blocks = (Bn + 127) / 128;           // 512 blocks of 128 threads

  lstm_fused_kernel<<<blocks, 128>>>(word, W_ih, W_hh, b_ih, b_hh,
                                     W_fc, b_fc, W_out, b_out, out, Bn);
}

// round 10
// speedup vs baseline: 1.5592x; 1.1597x over previous
#include <cuda_runtime.h>
#include <cstdint>
#include <cstddef>

#define TSTEPS 32
#define INF    27
#define HID    10

__device__ __forceinline__ void cp8(uint32_t saddr, const void* gptr){
  asm volatile("cp.async.ca.shared.global [%0], [%1], 8;" :: "r"(saddr), "l"(gptr));
}
// single-instruction tanh (MUFU.TANH, sm_75+)
__device__ __forceinline__ float tanh_fast(float x){
  float r;
  asm("tanh.approx.f32 %0, %1;" : "=f"(r) : "f"(x));
  return r;
}
// sigmoid from a PRE-HALVED preactivation: acc already holds x/2
//   sigma(x) = 0.5 + 0.5*tanh(x/2)  -> 1 MUFU + 1 FMA
__device__ __forceinline__ float sig_from_half(float acc_half){
  return fmaf(0.5f, tanh_fast(acc_half), 0.5f);
}

// 128 threads/block, 4 blocks/SM (single-wave residency: 592 slots >= 512 grid).
// Lane pairs (2p, 2p+1) share batch elements {2p, 2p+1}; lane parity selects
// which 5 hidden units it computes (split-k). MUFU.TANH activations with
// pre-halved i/f/o gate weights. Block-coop cp8 double-buffered x staging.
__global__ void __launch_bounds__(128, 4) lstm_fused_kernel(
    const float* __restrict__ word,
    const float* __restrict__ W_ih, const float* __restrict__ W_hh,
    const float* __restrict__ b_ih, const float* __restrict__ b_hh,
    const float* __restrict__ W_fc, const float* __restrict__ b_fc,
    const float* __restrict__ W_out, const float* __restrict__ b_out,
    float* __restrict__ out, int Bn)
{
  // scalar weights, rows padded for LDS.128-friendly immediate offsets.
  // Gate row order r in [0,40): [0,10)=i, [10,20)=f, [20,30)=g, [30,40)=o.
  // i/f/o rows stored pre-multiplied by 0.5 (sigmoid-via-tanh identity).
  __shared__ __align__(16) float s_wih[40*28];  // row r: r*28 + j, j<27, pad 0
  __shared__ __align__(16) float s_whh[40*12];  // row r: r*12 + j, j<10, pad 0
  __shared__ float s_bias[40];                  // (b_ih + b_hh), i/f/o halved
  __shared__ float s_wfc[50], s_bfc[5], s_wout[5], s_bout[1];
  __shared__ __align__(16) float s_x[2][128*INF];  // double-buffered x staging

  const int tid  = threadIdx.x;
  const int half = tid & 1;        // which 5 k's this lane owns (0..4 or 5..9)
  const int p    = tid >> 1;       // pair index (0..63)
  const int kb   = half * 5;

  for (int idx = tid; idx < 40*28; idx += 128){
    int r = idx / 28, j = idx - r*28;
    float sc = (r < 20 || r >= 30) ? 0.5f : 1.0f;   // halve i,f,o rows
    s_wih[idx] = (j < 27) ? sc * W_ih[r*27 + j] : 0.f;
  }
  for (int idx = tid; idx < 40*12; idx += 128){
    int r = idx / 12, j = idx - r*12;
    float sc = (r < 20 || r >= 30) ? 0.5f : 1.0f;
    s_whh[idx] = (j < 10) ? sc * W_hh[r*10 + j] : 0.f;
  }
  if (tid < 40){
    float sc = (tid < 20 || tid >= 30) ? 0.5f : 1.0f;
    s_bias[tid] = sc * (b_ih[tid] + b_hh[tid]);
  }
  if (tid < 50) s_wfc[tid] = W_fc[tid];
  if (tid < 5) { s_bfc[tid] = b_fc[tid]; s_wout[tid] = W_out[tid]; }
  if (tid == 0) s_bout[0] = b_out[0];

  const int blockElem = blockIdx.x * 128;
  const uint32_t sx0 = (uint32_t)__cvta_generic_to_shared(&s_x[0][0]);

  // stage t=0 into buffer 0 (1728 float2 per block-step, 128 threads)
  {
    const float2* src = (const float2*)(word + ((size_t)blockElem) * INF);
    #pragma unroll
    for (int m = 0; m < 14; m++){
      int i2 = m*128 + tid;
      if (i2 < 1728) cp8(sx0 + (uint32_t)(i2*8), src + i2);
    }
    asm volatile("cp.async.commit_group;");
  }

  // full h for both elements (rebuilt each step via shfl exchange),
  // own-c only (5 k x 2 elems)
  float hA[10], hB[10], cA[5], cB[5];
  #pragma unroll
  for (int k = 0; k < 10; k++){ hA[k]=0.f; hB[k]=0.f; }
  #pragma unroll
  for (int k = 0; k < 5;  k++){ cA[k]=0.f; cB[k]=0.f; }

  // lane-local weight bases (kb is uniform per lane; hoisted out of the loop)
  const float* wih_b  = s_wih + kb*28;
  const float* whh_b  = s_whh + kb*12;
  const float* bias_b = s_bias + kb;

  #pragma unroll 1
  for (int t = 0; t < TSTEPS; t++){
    if (t + 1 < TSTEPS){
      const float2* src = (const float2*)(word + ((size_t)(t+1)*Bn + blockElem) * INF);
      uint32_t dst = sx0 + (uint32_t)(((t+1)&1) * (128*INF*4));
      #pragma unroll
      for (int m = 0; m < 14; m++){
        int i2 = m*128 + tid;
        if (i2 < 1728) cp8(dst + (uint32_t)(i2*8), src + i2);
      }
      asm volatile("cp.async.commit_group;");
      asm volatile("cp.async.wait_group 1;");
    } else {
      asm volatile("cp.async.wait_group 0;");
    }
    __syncthreads();

    // x rows for pair elements 2p and 2p+1 (both lanes of a pair read the
    // same addresses -> 2-way broadcast; row stride 27 coprime w/ 32 banks)
    const float* xbA = &s_x[t & 1][(2*p    ) * INF];
    const float* xbB = &s_x[t & 1][(2*p + 1) * INF];
    float xA[27], xB[27];
    #pragma unroll
    for (int j = 0; j < 27; j++){ xA[j] = xbA[j]; xB[j] = xbB[j]; }

    float hnA[5], hnB[5];
    #pragma unroll
    for (int kk = 0; kk < 5; kk++){
      float ai0 = bias_b[kk],      ai1 = ai0;
      float af0 = bias_b[kk + 10], af1 = af0;
      float ag0 = bias_b[kk + 20], ag1 = ag0;
      float ao0 = bias_b[kk + 30], ao1 = ao0;
      #pragma unroll
      for (int j = 0; j < 27; j++){
        float wi = wih_b[(kk     )*28 + j];
        float wf = wih_b[(kk + 10)*28 + j];
        float wg = wih_b[(kk + 20)*28 + j];
        float wo = wih_b[(kk + 30)*28 + j];
        float xa = xA[j], xb = xB[j];
        ai0 = fmaf(wi, xa, ai0);  ai1 = fmaf(wi, xb, ai1);
        af0 = fmaf(wf, xa, af0);  af1 = fmaf(wf, xb, af1);
        ag0 = fmaf(wg, xa, ag0);  ag1 = fmaf(wg, xb, ag1);
        ao0 = fmaf(wo, xa, ao0);  ao1 = fmaf(wo, xb, ao1);
      }
      #pragma unroll
      for (int j = 0; j < 10; j++){
        float ui = whh_b[(kk     )*12 + j];
        float uf = whh_b[(kk + 10)*12 + j];
        float ug = whh_b[(kk + 20)*12 + j];
        float uo = whh_b[(kk + 30)*12 + j];
        float ha = hA[j], hb = hB[j];
        ai0 = fmaf(ui, ha, ai0);  ai1 = fmaf(ui, hb, ai1);
        af0 = fmaf(uf, ha, af0);  af1 = fmaf(uf, hb, af1);
        ag0 = fmaf(ug, ha, ag0);  ag1 = fmaf(ug, hb, ag1);
        ao0 = fmaf(uo, ha, ao0);  ao1 = fmaf(uo, hb, ao1);
      }
      // activations: i/f/o accs hold x/2 (pre-halved weights) -> 1 MUFU + 1 FMA
      float i0 = sig_from_half(ai0), i1 = sig_from_half(ai1);
      float f0 = sig_from_half(af0), f1 = sig_from_half(af1);
      float g0 = tanh_fast(ag0),     g1 = tanh_fast(ag1);
      float o0 = sig_from_half(ao0), o1 = sig_from_half(ao1);
      float cn0 = fmaf(f0, cA[kk], i0*g0);
      float cn1 = fmaf(f1, cB[kk], i1*g1);
      float hv0 = o0 * tanh_fast(cn0);
      float hv1 = o1 * tanh_fast(cn1);
      cA[kk]  = fmaxf(cn0, 0.f);       // ReLU on carried cell state
      cB[kk]  = fmaxf(cn1, 0.f);
      hnA[kk] = fmaxf(hv0, 0.f);       // ReLU on carried hidden
      hnB[kk] = fmaxf(hv1, 0.f);
    }
    // exchange halves with pair partner -> full h for both elements
    const int ob = 5 - kb;             // partner's k-base (0 <-> 5)
    #pragma unroll
    for (int kk = 0; kk < 5; kk++){
      float oA = __shfl_xor_sync(0xFFFFFFFFu, hnA[kk], 1);
      float oB = __shfl_xor_sync(0xFFFFFFFFu, hnB[kk], 1);
      hA[kb + kk] = hnA[kk];  hA[ob + kk] = oA;
      hB[kb + kk] = hnB[kk];  hB[ob + kk] = oB;
    }
    __syncthreads();   // all reads of this x buffer done before re-staging
  }

  // ---- head: FC(10->5) -> ReLU -> Linear(5->1) -> sigmoid ----
  if (half == 0){
    float z0 = s_bout[0], z1 = s_bout[0];
    #pragma unroll
    for (int u = 0; u < 5; u++){
      float y0 = s_bfc[u], y1 = s_bfc[u];
      #pragma unroll
      for (int k = 0; k < 10; k++){
        float w = s_wfc[u*10 + k];
        y0 = fmaf(w, hA[k], y0);
        y1 = fmaf(w, hB[k], y1);
      }
      z0 = fmaf(s_wout[u], fmaxf(y0, 0.f), z0);
      z1 = fmaf(s_wout[u], fmaxf(y1, 0.f), z1);
    }
    const int b0 = blockElem + 2*p;
    // final sigmoid (z not pre-halved): 0.5 + 0.5*tanh(z/2)
    if (b0 + 1 < Bn){
      float2 v;
      v.x = fmaf(0.5f, tanh_fast(0.5f * z0), 0.5f);
      v.y = fmaf(0.5f, tanh_fast(0.5f * z1), 0.5f);
      *(float2*)(out + b0) = v;                 // coalesced 8B store
    } else if (b0 < Bn){
      out[b0] = fmaf(0.5f, tanh_fast(0.5f * z0), 0.5f);
    }
  }
}

extern "C" void kernel_launch(void* const* d_in, const int* in_sizes, int n_in,
                              void* d_out, int out_size) {
  const float* word  = (const float*)d_in[0];
  const float* W_ih  = (const float*)d_in[1];
  const float* W_hh  = (const float*)d_in[2];
  const float* b_ih  = (const float*)d_in[3];
  const float* b_hh  = (const float*)d_in[4];
  const float* W_fc  = (const float*)d_in[5];
  const float* b_fc  = (const float*)d_in[6];
  const float* W_out = (const float*)d_in[7];
  const float* b_out = (const float*)d_in[8];
  float* out = (float*)d_out;

  const int Bn = in_sizes[0] / (TSTEPS * INF);   // 65536
  const int blocks = (Bn + 127) / 128;           // 512 blocks of 128 threads

  lstm_fused_kernel<<<blocks, 128>>>(word, W_ih, W_hh, b_ih, b_hh,
                                     W_fc, b_fc, W_out, b_out, out, Bn);
}